// round 8
// baseline (speedup 1.0000x reference)
#include <cuda_runtime.h>
#include <cstdint>

#define N_MAX 4096
#define W_MAX 128              // words per row (N_MAX/32)
#define FULLMASK 0xFFFFFFFFu

typedef unsigned long long u64;

// Static scratch (allocations forbidden).
__device__ float4   g_pos4[N_MAX];
__device__ int      g_count[N_MAX];
__device__ int      g_offset[N_MAX];
__device__ int      g_total;
__device__ int      g_done;
__device__ unsigned g_mask[N_MAX * W_MAX];   // 2 MB ballot bitmap, row-major words

// ---- packed f32x2 helpers (PTX f32x2 ops, sm_100+) ------------------------
__device__ __forceinline__ u64 pk2(float lo, float hi) {
    u64 r; asm("mov.b64 %0, {%1, %2};" : "=l"(r) : "f"(lo), "f"(hi)); return r;
}
__device__ __forceinline__ void upk2(u64 v, float& lo, float& hi) {
    asm("mov.b64 {%0, %1}, %2;" : "=f"(lo), "=f"(hi) : "l"(v));
}
__device__ __forceinline__ u64 add2(u64 a, u64 b) {
    u64 r; asm("add.rn.f32x2 %0, %1, %2;" : "=l"(r) : "l"(a), "l"(b)); return r;
}
__device__ __forceinline__ u64 mul2(u64 a, u64 b) {
    u64 r; asm("mul.rn.f32x2 %0, %1, %2;" : "=l"(r) : "l"(a), "l"(b)); return r;
}

__device__ __forceinline__ int warp_inc_scan(int v, int lane) {
#pragma unroll
    for (int off = 1; off < 32; off <<= 1) {
        int u = __shfl_up_sync(FULLMASK, v, off);
        if (lane >= off) v += u;
    }
    return v;
}

// ---------------------------------------------------------------------------
// Pack pos (N,3)+batch into float4; pad [n, n_pad) with per-row-distinct
// sentinel batch. Zeroes g_count (all rows) and g_done (graph-replay safe).
__global__ void pack_kernel(const float* __restrict__ pos,
                            const int* __restrict__ batch, int n, int n_pad) {
    int i = blockIdx.x * blockDim.x + threadIdx.x;
    if (i == 0) g_done = 0;
    if (i < N_MAX) g_count[i] = 0;
    if (i < n) {
        float4 p;
        p.x = pos[3 * i + 0];
        p.y = pos[3 * i + 1];
        p.z = pos[3 * i + 2];
        p.w = __int_as_float(batch[i]);
        g_pos4[i] = p;
    } else if (i < n_pad) {
        g_pos4[i] = make_float4(1e9f, 1e9f, 1e9f, __int_as_float(-2 - i));
    }
}

// ---------------------------------------------------------------------------
// Pass A: symmetric 32x32 tile evaluation (packed f32x2, 2 cols/step) +
// fused row counting + last-block offset scan (publishes g_total).
// Shared tile stored as NEGATED SoA so dx = pi + (-q) via add.rn.f32x2.
__global__ void mask_fused_kernel(int nw) {
    int I = blockIdx.y;
    int wslot = threadIdx.x >> 5;
    int J = blockIdx.x * 8 + wslot;
    int lane = threadIdx.x & 31;
    int nblocks = gridDim.x * gridDim.y;

    __shared__ float sx[8][32], sy[8][32], sz[8][32];
    __shared__ int   sb[8][32];

    bool valid = (J < nw) & (J >= I);
    if (valid) {
        float4 pi = g_pos4[I * 32 + lane];
        {
            float4 q = g_pos4[J * 32 + lane];
            sx[wslot][lane] = -q.x;
            sy[wslot][lane] = -q.y;
            sz[wslot][lane] = -q.z;
            sb[wslot][lane] = __float_as_int(q.w);
        }
        __syncwarp();
        int ib = __float_as_int(pi.w);

        unsigned myword = 0;
        if (I == J) {                      // diagonal: scalar path with k!=lane
#pragma unroll 8
            for (int k = 0; k < 32; k++) {
                float dx = __fadd_rn(pi.x, sx[wslot][k]);
                float dy = __fadd_rn(pi.y, sy[wslot][k]);
                float dz = __fadd_rn(pi.z, sz[wslot][k]);
                float d2 = __fadd_rn(__fadd_rn(__fmul_rn(dx, dx), __fmul_rn(dy, dy)),
                                     __fmul_rn(dz, dz));
                bool p = (ib == sb[wslot][k]) & (d2 < 25.0f) & (k != lane);
                if (p) p = (__fsqrt_rn(d2) < 5.0f);
                myword |= ((unsigned)p) << k;
            }
            g_mask[(size_t)(I * 32 + lane) * nw + J] = myword;
            int pc = __popc(myword);
            if (pc) atomicAdd(&g_count[I * 32 + lane], pc);
        } else {                           // off-diagonal: packed 2 cols/step
            u64 pix2 = pk2(pi.x, pi.x);
            u64 piy2 = pk2(pi.y, pi.y);
            u64 piz2 = pk2(pi.z, pi.z);
            unsigned tword = 0;
            const u64* nx2 = reinterpret_cast<const u64*>(sx[wslot]);
            const u64* ny2 = reinterpret_cast<const u64*>(sy[wslot]);
            const u64* nz2 = reinterpret_cast<const u64*>(sz[wslot]);
#pragma unroll 4
            for (int k2 = 0; k2 < 16; k2++) {
                u64 dx2 = add2(pix2, nx2[k2]);
                u64 dy2 = add2(piy2, ny2[k2]);
                u64 dz2 = add2(piz2, nz2[k2]);
                u64 d2p = add2(add2(mul2(dx2, dx2), mul2(dy2, dy2)),
                               mul2(dz2, dz2));
                float d2a, d2b;
                upk2(d2p, d2a, d2b);
                int k = k2 * 2;
                bool p0 = (ib == sb[wslot][k])     & (d2a < 25.0f);
                bool p1 = (ib == sb[wslot][k + 1]) & (d2b < 25.0f);
                if (p0) p0 = (__fsqrt_rn(d2a) < 5.0f);
                if (p1) p1 = (__fsqrt_rn(d2b) < 5.0f);
                unsigned b0 = __ballot_sync(FULLMASK, p0);
                unsigned b1 = __ballot_sync(FULLMASK, p1);
                myword |= ((unsigned)p0) << k;
                myword |= ((unsigned)p1) << (k + 1);
                if (lane == k)     tword = b0;     // transposed row J*32+k
                if (lane == k + 1) tword = b1;
            }
            g_mask[(size_t)(I * 32 + lane) * nw + J] = myword;
            g_mask[(size_t)(J * 32 + lane) * nw + I] = tword;
            int pc0 = __popc(myword);
            int pc1 = __popc(tword);
            if (pc0) atomicAdd(&g_count[I * 32 + lane], pc0);
            if (pc1) atomicAdd(&g_count[J * 32 + lane], pc1);
        }
    }

    // --- last block performs the offset scan ---
    __shared__ int s_last;
    __shared__ int wsum[8];
    __threadfence();
    __syncthreads();
    if (threadIdx.x == 0)
        s_last = (atomicAdd(&g_done, 1) == nblocks - 1) ? 1 : 0;
    __syncthreads();
    if (s_last) {
        __threadfence();
        int t = threadIdx.x;               // 256 threads x 16 counts = 4096
        int tl = t & 31, tw = t >> 5;
        int v[16];
#pragma unroll
        for (int k = 0; k < 4; k++) {
            int4 c = reinterpret_cast<int4*>(g_count)[t * 4 + k];
            v[k * 4 + 0] = c.x; v[k * 4 + 1] = c.y;
            v[k * 4 + 2] = c.z; v[k * 4 + 3] = c.w;
        }
        int tot = 0;
        int pre[16];
#pragma unroll
        for (int k = 0; k < 16; k++) { pre[k] = tot; tot += v[k]; }
        int inc = warp_inc_scan(tot, tl);
        if (tl == 31) wsum[tw] = inc;
        __syncthreads();
        if (tw == 0) {
            int x = (tl < 8) ? wsum[tl] : 0;
            x = warp_inc_scan(x, tl);
            if (tl < 8) wsum[tl] = x;
        }
        __syncthreads();
        int base = (tw ? wsum[tw - 1] : 0) + (inc - tot);
#pragma unroll
        for (int k = 0; k < 4; k++) {
            int4 o;
            o.x = base + pre[k * 4 + 0];
            o.y = base + pre[k * 4 + 1];
            o.z = base + pre[k * 4 + 2];
            o.w = base + pre[k * 4 + 3];
            reinterpret_cast<int4*>(g_offset)[t * 4 + k] = o;
        }
        if (t == 255) g_total = base + pre[15] + v[15];
    }
}

// ---------------------------------------------------------------------------
// Tail init (post-scan): write only slots >= g_total. Compare-only (no div).
// Regions: [0,mp)=-1, [mp,2mp)=-1, [2mp,3mp)=0, [3mp,6mp)=0 (vec, 3/slot).
__global__ void tail_init_kernel(float* __restrict__ out, int mp) {
    long long e = (long long)(blockIdx.x * (long long)blockDim.x + threadIdx.x) * 4;
    long long total6 = 6LL * mp;
    if (e >= total6) return;
    int tt = g_total;
    if (tt > mp) tt = mp;
    long long m1 = mp, m2 = 2LL * mp, m3 = 3LL * mp;
    long long rbase, bound;
    float val;
    if (e < m1)      { rbase = 0;  bound = tt;            val = -1.0f; }
    else if (e < m2) { rbase = m1; bound = m1 + tt;       val = -1.0f; }
    else if (e < m3) { rbase = m2; bound = m2 + tt;       val =  0.0f; }
    else             { rbase = m3; bound = m3 + 3LL * tt; val =  0.0f; }
    (void)rbase;
    if (e >= bound) {
        *reinterpret_cast<float4*>(out + e) = make_float4(val, val, val, val);
    } else if (e + 3 >= bound) {
#pragma unroll
        for (int k = 0; k < 4; k++)
            if (e + k >= bound) out[e + k] = val;
    }
}

// ---------------------------------------------------------------------------
// Pass B: expand persisted masks (diagonal pre-cleared). One warp per row.
__global__ void fill_kernel(float* __restrict__ out, int n, int mp, int nw) {
    int row = (blockIdx.x * blockDim.x + threadIdx.x) >> 5;
    int lane = threadIdx.x & 31;
    if (row >= n) return;
    float4 pi = g_pos4[row];
    const unsigned* mrow = g_mask + (size_t)row * nw;
    int base = g_offset[row];
    float fi = (float)row;
    for (int w0 = 0; w0 < nw; w0 += 32) {
        unsigned m = mrow[w0 + lane];
        int pc = __popc(m);
        int inc = warp_inc_scan(pc, lane);
        int tot = __shfl_sync(FULLMASK, inc, 31);
        int slot = base + inc - pc;
        while (m) {
            int b = __ffs(m) - 1;
            m &= m - 1;
            int j = (w0 + lane) * 32 + b;
            float4 pj = g_pos4[j];
            float dx = __fadd_rn(pi.x, -pj.x);
            float dy = __fadd_rn(pi.y, -pj.y);
            float dz = __fadd_rn(pi.z, -pj.z);
            float d2 = __fadd_rn(__fadd_rn(__fmul_rn(dx, dx), __fmul_rn(dy, dy)),
                                 __fmul_rn(dz, dz));
            if (slot < mp) {
                out[slot]          = fi;
                out[mp + slot]     = (float)j;
                out[2 * mp + slot] = __fsqrt_rn(d2);
                float* v = out + 3 * mp + 3 * slot;
                v[0] = dx; v[1] = dy; v[2] = dz;
            }
            slot++;
        }
        base += tot;
    }
}

// ---------------------------------------------------------------------------
extern "C" void kernel_launch(void* const* d_in, const int* in_sizes, int n_in,
                              void* d_out, int out_size) {
    const float* pos   = (const float*)d_in[0];
    const int*   batch = (const int*)d_in[1];
    float* out = (float*)d_out;

    int n = in_sizes[1];
    if (n > N_MAX) n = N_MAX;
    int n_pad = (n + 31) & ~31;
    int nw = n_pad / 32;
    int mp = out_size / 6;

    pack_kernel<<<(N_MAX + 255) / 256, 256>>>(pos, batch, n, n_pad);

    dim3 mgrid((nw + 7) / 8, nw);
    mask_fused_kernel<<<mgrid, 256>>>(nw);

    long long vec4 = (6LL * mp) / 4;
    tail_init_kernel<<<(int)((vec4 + 255) / 256), 256>>>(out, mp);

    fill_kernel<<<(n * 32 + 255) / 256, 256>>>(out, n, mp, nw);
}

// round 9
// speedup vs baseline: 1.0198x; 1.0198x over previous
#include <cuda_runtime.h>
#include <cstdint>

#define N_MAX 4096
#define W_MAX 128              // words per row (N_MAX/32)
#define NQ    (N_MAX * 4)     // row-quarter count entries
#define FULLMASK 0xFFFFFFFFu

// Static scratch (allocations forbidden).
__device__ float4   g_pos4[N_MAX];
__device__ int      g_countq[NQ];    // per (row, quarter) pair counts
__device__ int      g_offsetq[NQ];   // exclusive scan of g_countq
__device__ unsigned g_mask[N_MAX * W_MAX];   // 2 MB ballot bitmap, row-major words

__device__ __forceinline__ int warp_inc_scan(int v, int lane) {
#pragma unroll
    for (int off = 1; off < 32; off <<= 1) {
        int u = __shfl_up_sync(FULLMASK, v, off);
        if (lane >= off) v += u;
    }
    return v;
}

// ---------------------------------------------------------------------------
// Pack pos (N,3)+batch into float4; pad [n, n_pad) with per-row-distinct
// sentinel batch. Zeroes g_countq (graph-replay safe).
__global__ void pack_kernel(const float* __restrict__ pos,
                            const int* __restrict__ batch, int n, int n_pad) {
    int i = blockIdx.x * blockDim.x + threadIdx.x;
    if (i < N_MAX)
        reinterpret_cast<int4*>(g_countq)[i] = make_int4(0, 0, 0, 0);
    if (i < n) {
        float4 p;
        p.x = pos[3 * i + 0];
        p.y = pos[3 * i + 1];
        p.z = pos[3 * i + 2];
        p.w = __int_as_float(batch[i]);
        g_pos4[i] = p;
    } else if (i < n_pad) {
        g_pos4[i] = make_float4(1e9f, 1e9f, 1e9f, __int_as_float(-2 - i));
    }
}

// Full output init: edge_index = -1, weight/vec = 0.
__global__ void init_kernel(float* __restrict__ out, int mp) {
    long long idx = (long long)(blockIdx.x * (long long)blockDim.x + threadIdx.x) * 4;
    if (idx < 6LL * mp) {
        float v = (idx < 2LL * mp) ? -1.0f : 0.0f;
        *reinterpret_cast<float4*>(out + idx) = make_float4(v, v, v, v);
    }
}

// ---------------------------------------------------------------------------
// Pass A: symmetric 32x32 tile evaluation + fused per-quarter counting.
// One warp per tile (I,J), J>=I. Lane l owns row i=I*32+l. Step k evaluates
// column j=J*32+k. Local word = row block; ballot = transposed block.
__global__ void mask_block_kernel(int nw) {
    int I = blockIdx.y;
    int wslot = threadIdx.x >> 5;
    int J = blockIdx.x * 8 + wslot;
    int lane = threadIdx.x & 31;
    if (J >= nw || J < I) return;

    __shared__ float4 sh[8][32];
    float4 pi = g_pos4[I * 32 + lane];
    sh[wslot][lane] = g_pos4[J * 32 + lane];
    __syncwarp();
    int ib = __float_as_int(pi.w);

    unsigned myword = 0;
    if (I == J) {
#pragma unroll 8
        for (int k = 0; k < 32; k++) {
            float4 q = sh[wslot][k];
            float dx = __fadd_rn(pi.x, -q.x);
            float dy = __fadd_rn(pi.y, -q.y);
            float dz = __fadd_rn(pi.z, -q.z);
            float d2 = __fadd_rn(__fadd_rn(__fmul_rn(dx, dx), __fmul_rn(dy, dy)),
                                 __fmul_rn(dz, dz));
            bool p = (ib == __float_as_int(q.w)) & (d2 < 25.0f) & (k != lane);
            if (p) p = (__fsqrt_rn(d2) < 5.0f);
            myword |= ((unsigned)p) << k;
        }
        g_mask[(size_t)(I * 32 + lane) * nw + J] = myword;
        int pc = __popc(myword);
        if (pc) atomicAdd(&g_countq[(I * 32 + lane) * 4 + (J >> 5)], pc);
    } else {
        unsigned tword = 0;
#pragma unroll 8
        for (int k = 0; k < 32; k++) {
            float4 q = sh[wslot][k];
            float dx = __fadd_rn(pi.x, -q.x);
            float dy = __fadd_rn(pi.y, -q.y);
            float dz = __fadd_rn(pi.z, -q.z);
            float d2 = __fadd_rn(__fadd_rn(__fmul_rn(dx, dx), __fmul_rn(dy, dy)),
                                 __fmul_rn(dz, dz));
            bool p = (ib == __float_as_int(q.w)) & (d2 < 25.0f);
            if (p) p = (__fsqrt_rn(d2) < 5.0f);
            unsigned bal = __ballot_sync(FULLMASK, p);   // bit m = pred(I*32+m, j)
            myword |= ((unsigned)p) << k;
            if (lane == k) tword = bal;                  // row J*32+k, word I
        }
        g_mask[(size_t)(I * 32 + lane) * nw + J] = myword;
        g_mask[(size_t)(J * 32 + lane) * nw + I] = tword;
        int pc0 = __popc(myword);
        int pc1 = __popc(tword);
        if (pc0) atomicAdd(&g_countq[(I * 32 + lane) * 4 + (J >> 5)], pc0);
        if (pc1) atomicAdd(&g_countq[(J * 32 + lane) * 4 + (I >> 5)], pc1);
    }
}

// ---------------------------------------------------------------------------
// Exclusive scan of 16384 quarter-counts: 1024 threads x 16 (shfl, 2 barriers).
__global__ void scan_kernel() {
    __shared__ int wsum[32];
    int t = threadIdx.x;
    int lane = t & 31, w = t >> 5;
    int v[16];
#pragma unroll
    for (int k = 0; k < 4; k++) {
        int4 c = reinterpret_cast<int4*>(g_countq)[t * 4 + k];
        v[k * 4 + 0] = c.x; v[k * 4 + 1] = c.y;
        v[k * 4 + 2] = c.z; v[k * 4 + 3] = c.w;
    }
    int tot = 0;
    int pre[16];
#pragma unroll
    for (int k = 0; k < 16; k++) { pre[k] = tot; tot += v[k]; }
    int inc = warp_inc_scan(tot, lane);
    if (lane == 31) wsum[w] = inc;
    __syncthreads();
    if (w == 0) {
        int x = warp_inc_scan(wsum[lane], lane);
        wsum[lane] = x;
    }
    __syncthreads();
    int base = (w ? wsum[w - 1] : 0) + (inc - tot);
#pragma unroll
    for (int k = 0; k < 4; k++) {
        int4 o;
        o.x = base + pre[k * 4 + 0];
        o.y = base + pre[k * 4 + 1];
        o.z = base + pre[k * 4 + 2];
        o.w = base + pre[k * 4 + 3];
        reinterpret_cast<int4*>(g_offsetq)[t * 4 + k] = o;
    }
}

// ---------------------------------------------------------------------------
// Pass B: expand persisted masks. One warp per (row, quarter): 32 words,
// no outer loop. Canonical order preserved by (row, quarter) scan order.
__global__ void fill_kernel(float* __restrict__ out, int n, int mp, int nw) {
    int wid  = (blockIdx.x * blockDim.x + threadIdx.x) >> 5;
    int lane = threadIdx.x & 31;
    int row = wid >> 2;
    int q   = wid & 3;
    if (row >= n) return;
    float4 pi = g_pos4[row];
    unsigned m = g_mask[(size_t)row * nw + q * 32 + lane];
    int pc = __popc(m);
    int inc = warp_inc_scan(pc, lane);
    int slot = g_offsetq[wid] + inc - pc;
    float fi = (float)row;
    int jbase = (q * 32 + lane) * 32;
    while (m) {
        int b = __ffs(m) - 1;
        m &= m - 1;
        int j = jbase + b;
        float4 pj = g_pos4[j];
        float dx = __fadd_rn(pi.x, -pj.x);
        float dy = __fadd_rn(pi.y, -pj.y);
        float dz = __fadd_rn(pi.z, -pj.z);
        float d2 = __fadd_rn(__fadd_rn(__fmul_rn(dx, dx), __fmul_rn(dy, dy)),
                             __fmul_rn(dz, dz));
        if (slot < mp) {
            out[slot]          = fi;
            out[mp + slot]     = (float)j;
            out[2 * mp + slot] = __fsqrt_rn(d2);
            float* v = out + 3 * mp + 3 * slot;
            v[0] = dx; v[1] = dy; v[2] = dz;
        }
        slot++;
    }
}

// ---------------------------------------------------------------------------
extern "C" void kernel_launch(void* const* d_in, const int* in_sizes, int n_in,
                              void* d_out, int out_size) {
    const float* pos   = (const float*)d_in[0];
    const int*   batch = (const int*)d_in[1];
    float* out = (float*)d_out;

    int n = in_sizes[1];
    if (n > N_MAX) n = N_MAX;
    int n_pad = (n + 31) & ~31;
    int nw = n_pad / 32;
    int mp = out_size / 6;

    pack_kernel<<<(N_MAX + 255) / 256, 256>>>(pos, batch, n, n_pad);

    long long vec4 = (6LL * mp) / 4;
    init_kernel<<<(int)((vec4 + 255) / 256), 256>>>(out, mp);

    dim3 mgrid((nw + 7) / 8, nw);
    mask_block_kernel<<<mgrid, 256>>>(nw);

    scan_kernel<<<1, 1024>>>();

    fill_kernel<<<(n * 4 * 32 + 255) / 256, 256>>>(out, n, mp, nw);
}